// round 1
// baseline (speedup 1.0000x reference)
#include <cuda_runtime.h>
#include <math.h>

// Problem constants (fixed by setup_inputs)
#define BB   16
#define NT   300
#define NCC  80
#define IMGS 640.0f

__device__ double g_sp[3];      // sum softplus(obj logits) per scale
__device__ double g_objsub[3];  // sum of obj logits at unique marked cells
__device__ double g_box[3];
__device__ double g_cls[3];
__device__ double g_nkeep[3];

__constant__ float c_anchors[3][3][2] = {
    {{10.f,13.f},{16.f,30.f},{33.f,23.f}},
    {{30.f,61.f},{62.f,45.f},{59.f,119.f}},
    {{116.f,90.f},{156.f,198.f},{373.f,326.f}}
};
__constant__ float c_stride[3] = {8.f, 16.f, 32.f};
__constant__ int   c_G[3]      = {80, 40, 20};

__device__ __forceinline__ float softplusf(float x) {
    // log1p(exp(-|x|)) + max(x,0)  (stable softplus)
    float ax = fabsf(x);
    return log1pf(__expf(-ax)) + fmaxf(x, 0.0f);
}
__device__ __forceinline__ float sigmoidf(float x) {
    return 1.0f / (1.0f + __expf(-x));
}

// ---------------------------------------------------------------------------
// Kernel 1: per-(anchor,target) pair losses + dedup'd obj subtraction.
// One block per scale, 1024 threads (900 active pairs).
// ---------------------------------------------------------------------------
__global__ void pairs_kernel(const float* __restrict__ p0,
                             const float* __restrict__ p1,
                             const float* __restrict__ p2,
                             const float* __restrict__ tgt)
{
    const int s = blockIdx.x;
    const float* pred = (s == 0) ? p0 : ((s == 1) ? p1 : p2);
    const int   G  = c_G[s];
    const int   GG = G * G;
    const float stride = c_stride[s];

    __shared__ float         st[NT][6];
    __shared__ int           sbi[NT], sgi[NT], sgj[NT];
    __shared__ unsigned char skeep[3 * NT];
    __shared__ double        sred[32][4];

    const int tid = threadIdx.x;

    if (tid == 0) g_sp[s] = 0.0;   // zero accumulator for obj_kernel (next launch)

    for (int i = tid; i < NT * 6; i += blockDim.x)
        ((float*)st)[i] = tgt[i];
    __syncthreads();

    if (tid < NT) {
        float cx = st[tid][2] * (float)G;
        float cy = st[tid][3] * (float)G;
        int gi = (int)cx; gi = min(max(gi, 0), G - 1);
        int gj = (int)cy; gj = min(max(gj, 0), G - 1);
        sgi[tid] = gi; sgj[tid] = gj;
        sbi[tid] = (int)st[tid][0];
    }
    for (int t = tid; t < 3 * NT; t += blockDim.x) {
        int a = t / NT, n = t - a * NT;
        float gw = st[n][4] * IMGS, gh = st[n][5] * IMGS;
        float rw = gw / c_anchors[s][a][0];
        float rh = gh / c_anchors[s][a][1];
        float m = fmaxf(fmaxf(rw, 1.0f / fmaxf(rw, 1e-8f)),
                        fmaxf(rh, 1.0f / fmaxf(rh, 1e-8f)));
        skeep[t] = (m < 4.0f) ? 1 : 0;
    }
    __syncthreads();

    float kf = 0.0f, lbox = 0.0f, lcls = 0.0f, lobjsub = 0.0f;

    if (tid < 3 * NT && skeep[tid]) {
        const int a = tid / NT, n = tid - a * NT;
        kf = 1.0f;
        const int b  = sbi[n];
        const int gi = sgi[n];
        const int gj = sgj[n];
        const float* base = pred + ((long)b * 255 + (long)a * 85) * GG + (long)gj * G + gi;

        // dedup: first kept pair mapping to this (a,b,gj,gi) cell wins
        bool first = true;
        for (int m2 = 0; m2 < n; m2++) {
            if (skeep[a * NT + m2] && sbi[m2] == b && sgi[m2] == gi && sgj[m2] == gj) {
                first = false; break;
            }
        }
        if (first) lobjsub = base[0];

        // ---- box (CIoU) ----
        float px = base[(long)1 * GG];
        float py = base[(long)2 * GG];
        float pw = base[(long)3 * GG];
        float ph = base[(long)4 * GG];
        float pcx = sigmoidf(px) + (float)gi;
        float pcy = sigmoidf(py) + (float)gj;
        float aw = c_anchors[s][a][0] / stride;
        float ah = c_anchors[s][a][1] / stride;
        float pbw = __expf(fminf(fmaxf(pw, -4.0f), 4.0f)) * aw;
        float pbh = __expf(fminf(fmaxf(ph, -4.0f), 4.0f)) * ah;

        float b1x0 = (pcx - pbw * 0.5f) * stride;
        float b1y0 = (pcy - pbh * 0.5f) * stride;
        float b1x1 = (pcx + pbw * 0.5f) * stride;
        float b1y1 = (pcy + pbh * 0.5f) * stride;

        float tcx = st[n][2] * (float)G;
        float tcy = st[n][3] * (float)G;
        float tgw = st[n][4] * (float)G;
        float tgh = st[n][5] * (float)G;
        float b2x0 = (tcx - tgw * 0.5f) * stride;
        float b2y0 = (tcy - tgh * 0.5f) * stride;
        float b2x1 = (tcx + tgw * 0.5f) * stride;
        float b2y1 = (tcy + tgh * 0.5f) * stride;

        const float eps = 1e-7f;
        float w1 = b1x1 - b1x0, h1 = b1y1 - b1y0;
        float w2 = b2x1 - b2x0, h2 = b2y1 - b2y0;
        float ix = fmaxf(fminf(b1x1, b2x1) - fmaxf(b1x0, b2x0), 0.0f);
        float iy = fmaxf(fminf(b1y1, b2y1) - fmaxf(b1y0, b2y0), 0.0f);
        float inter = ix * iy;
        float uni = w1 * h1 + w2 * h2 - inter + eps;
        float iou = inter / uni;
        float cw = fmaxf(b1x1, b2x1) - fminf(b1x0, b2x0);
        float ch = fmaxf(b1y1, b2y1) - fminf(b1y0, b2y0);
        float c2 = cw * cw + ch * ch + eps;
        float dx = b2x0 + b2x1 - b1x0 - b1x1;
        float dy = b2y0 + b2y1 - b1y0 - b1y1;
        float rho2 = (dx * dx + dy * dy) * 0.25f;
        const float k4pi2 = 4.0f / (float)(M_PI * M_PI);
        float da = atanf(w2 / (h2 + eps)) - atanf(w1 / (h1 + eps));
        float v = k4pi2 * da * da;
        float alpha = v / (v - iou + (1.0f + eps));
        float ciou = iou - (rho2 / c2 + v * alpha);
        lbox = 1.0f - ciou;

        // ---- cls BCE ----
        int cls = (int)st[n][1];
        float csum = 0.0f;
        #pragma unroll 4
        for (int c = 0; c < NCC; c++) {
            float l = base[(long)(5 + c) * GG];
            csum += softplusf(l) - ((c == cls) ? l : 0.0f);
        }
        lcls = csum;
    }

    // ---- block reduction (double) ----
    double v0 = (double)kf, v1 = (double)lbox, v2 = (double)lcls, v3 = (double)lobjsub;
    #pragma unroll
    for (int o = 16; o > 0; o >>= 1) {
        v0 += __shfl_down_sync(0xFFFFFFFF, v0, o);
        v1 += __shfl_down_sync(0xFFFFFFFF, v1, o);
        v2 += __shfl_down_sync(0xFFFFFFFF, v2, o);
        v3 += __shfl_down_sync(0xFFFFFFFF, v3, o);
    }
    int warp = tid >> 5, lane = tid & 31;
    if (lane == 0) {
        sred[warp][0] = v0; sred[warp][1] = v1;
        sred[warp][2] = v2; sred[warp][3] = v3;
    }
    __syncthreads();
    if (warp == 0) {
        double a0 = sred[lane][0], a1 = sred[lane][1], a2 = sred[lane][2], a3 = sred[lane][3];
        #pragma unroll
        for (int o = 16; o > 0; o >>= 1) {
            a0 += __shfl_down_sync(0xFFFFFFFF, a0, o);
            a1 += __shfl_down_sync(0xFFFFFFFF, a1, o);
            a2 += __shfl_down_sync(0xFFFFFFFF, a2, o);
            a3 += __shfl_down_sync(0xFFFFFFFF, a3, o);
        }
        if (lane == 0) {
            g_nkeep[s]  = a0;
            g_box[s]    = a1;
            g_cls[s]    = a2;
            g_objsub[s] = a3;
        }
    }
}

// ---------------------------------------------------------------------------
// Kernel 2: sum softplus over the objectness channel of every scale.
// grid = (300, 3), block = 256. float4 loads.
// ---------------------------------------------------------------------------
__global__ void obj_kernel(const float* __restrict__ p0,
                           const float* __restrict__ p1,
                           const float* __restrict__ p2)
{
    const int s = blockIdx.y;
    const float* pred = (s == 0) ? p0 : ((s == 1) ? p1 : p2);
    const int G  = c_G[s];
    const int GG = G * G;
    const int total4 = (BB * 3 * GG) >> 2;

    double acc = 0.0;
    for (int i = blockIdx.x * blockDim.x + threadIdx.x; i < total4;
         i += gridDim.x * blockDim.x) {
        int idx = i << 2;
        int plane = idx / GG;
        int w = idx - plane * GG;
        int b = plane / 3;
        int a = plane - b * 3;
        const float4 v = *(const float4*)(pred + ((long)b * 255 + (long)a * 85) * GG + w);
        acc += (double)(softplusf(v.x) + softplusf(v.y) + softplusf(v.z) + softplusf(v.w));
    }

    // block reduce
    #pragma unroll
    for (int o = 16; o > 0; o >>= 1)
        acc += __shfl_down_sync(0xFFFFFFFF, acc, o);
    __shared__ double sw[8];
    int warp = threadIdx.x >> 5, lane = threadIdx.x & 31;
    if (lane == 0) sw[warp] = acc;
    __syncthreads();
    if (warp == 0) {
        double a0 = (lane < (blockDim.x >> 5)) ? sw[lane] : 0.0;
        #pragma unroll
        for (int o = 4; o > 0; o >>= 1)
            a0 += __shfl_down_sync(0xFFFFFFFF, a0, o);
        if (lane == 0) atomicAdd(&g_sp[s], a0);
    }
}

// ---------------------------------------------------------------------------
// Kernel 3: combine
// ---------------------------------------------------------------------------
__global__ void finalize_kernel(float* __restrict__ out)
{
    double tot = 0.0;
    #pragma unroll
    for (int s = 0; s < 3; s++) {
        double M  = (double)BB * 3.0 * (double)c_G[s] * (double)c_G[s];
        double nk = fmax(g_nkeep[s], 1.0);
        double loss_box = g_box[s] / nk;
        double loss_obj = (g_sp[s] - g_objsub[s]) / M;
        double loss_cls = g_cls[s] / (nk * (double)NCC);
        tot += 0.05 * loss_box + 1.0 * loss_obj + 0.5 * loss_cls;
    }
    out[0] = (float)tot;
}

extern "C" void kernel_launch(void* const* d_in, const int* in_sizes, int n_in,
                              void* d_out, int out_size)
{
    const float* p0  = (const float*)d_in[0];
    const float* p1  = (const float*)d_in[1];
    const float* p2  = (const float*)d_in[2];
    const float* tgt = (const float*)d_in[3];
    float* out = (float*)d_out;

    pairs_kernel<<<3, 1024>>>(p0, p1, p2, tgt);
    obj_kernel<<<dim3(300, 3), 256>>>(p0, p1, p2);
    finalize_kernel<<<1, 1>>>(out);
}

// round 2
// speedup vs baseline: 1.9305x; 1.9305x over previous
#include <cuda_runtime.h>
#include <math.h>

#define BB   16
#define NT   300
#define NCC  80
#define IMGS 640.0f

#define PAIR_BLOCKS_PER_SCALE 57          // 57*16 warps = 912 >= 900 pairs
#define PAIR_BLOCKS (3 * PAIR_BLOCKS_PER_SCALE)   // 171
#define OBJ_TOTAL4  100800                // total float4 elems in obj channels (all scales)
#define OBJ_BLOCKS  197                   // 197*512 = 100864 >= 100800
#define TOTAL_BLOCKS (PAIR_BLOCKS + OBJ_BLOCKS)   // 368
#define BLOCK 512

__device__ double g_sp[3]     = {0,0,0};
__device__ double g_objsub[3] = {0,0,0};
__device__ double g_box[3]    = {0,0,0};
__device__ double g_cls[3]    = {0,0,0};
__device__ double g_nkeep[3]  = {0,0,0};
__device__ unsigned int g_done = 0;

__constant__ float c_anchors[3][3][2] = {
    {{10.f,13.f},{16.f,30.f},{33.f,23.f}},
    {{30.f,61.f},{62.f,45.f},{59.f,119.f}},
    {{116.f,90.f},{156.f,198.f},{373.f,326.f}}
};
__constant__ float c_stride[3] = {8.f, 16.f, 32.f};
__constant__ int   c_G[3]      = {80, 40, 20};

__device__ __forceinline__ float softplusf(float x) {
    float ax = fabsf(x);
    return log1pf(__expf(-ax)) + fmaxf(x, 0.0f);
}
__device__ __forceinline__ float sigmoidf(float x) {
    return 1.0f / (1.0f + __expf(-x));
}
__device__ __forceinline__ double atomic_read(double* p) {
    return atomicAdd(p, 0.0);
}

__global__ void __launch_bounds__(BLOCK)
fused_loss_kernel(const float* __restrict__ p0,
                  const float* __restrict__ p1,
                  const float* __restrict__ p2,
                  const float* __restrict__ tgt,
                  float* __restrict__ out)
{
    __shared__ float scx[NT], scy[NT], sgw[NT], sgh[NT];
    __shared__ int   sbi[NT], scls[NT], sgi[NT], sgj[NT];
    __shared__ unsigned char skeep[3 * NT];
    __shared__ double sacc[4];   // pairs: nkeep, box, cls, objsub
    __shared__ double ssp[3];    // obj:   softplus sum per scale

    const int tid = threadIdx.x;
    const int bx  = blockIdx.x;

    if (tid < 4) sacc[tid] = 0.0;
    else if (tid < 7) ssp[tid - 4] = 0.0;

    if (bx < PAIR_BLOCKS) {
        // =============== PAIR BLOCKS ===============
        const int s    = bx / PAIR_BLOCKS_PER_SCALE;
        const int slot = bx - s * PAIR_BLOCKS_PER_SCALE;
        const float* pred = (s == 0) ? p0 : ((s == 1) ? p1 : p2);
        const int   G  = c_G[s];
        const int   GG = G * G;
        const float stride = c_stride[s];

        // cooperative target setup
        for (int n = tid; n < NT; n += BLOCK) {
            float bi = tgt[n * 6 + 0];
            float cl = tgt[n * 6 + 1];
            float tx = tgt[n * 6 + 2];
            float ty = tgt[n * 6 + 3];
            float tw = tgt[n * 6 + 4];
            float th = tgt[n * 6 + 5];
            float cx = tx * (float)G;
            float cy = ty * (float)G;
            int gi = (int)cx; gi = min(max(gi, 0), G - 1);
            int gj = (int)cy; gj = min(max(gj, 0), G - 1);
            scx[n] = cx; scy[n] = cy;
            sgw[n] = tw * (float)G; sgh[n] = th * (float)G;
            sbi[n] = (int)bi; scls[n] = (int)cl;
            sgi[n] = gi; sgj[n] = gj;
            // keep flags for the 3 anchors of this scale
            float gw = tw * IMGS, gh = th * IMGS;
            #pragma unroll
            for (int a = 0; a < 3; a++) {
                float rw = gw / c_anchors[s][a][0];
                float rh = gh / c_anchors[s][a][1];
                float m = fmaxf(fmaxf(rw, 1.0f / fmaxf(rw, 1e-8f)),
                                fmaxf(rh, 1.0f / fmaxf(rh, 1e-8f)));
                skeep[a * NT + n] = (m < 4.0f) ? 1 : 0;
            }
        }
        __syncthreads();

        const int warp = tid >> 5, lane = tid & 31;
        const int t = slot * 16 + warp;            // pair id in [0, 912)

        if (t < 3 * NT && skeep[t]) {
            const int a = t / NT, n = t - a * NT;
            const int b  = sbi[n];
            const int gi = sgi[n];
            const int gj = sgj[n];
            const float* base = pred + ((long)b * 255 + (long)a * 85) * GG
                                     + (long)gj * G + gi;

            // lane-parallel gather of 85 channels (3 per lane)
            float v0 = __ldg(base + (long)lane * GG);
            float v1 = __ldg(base + (long)(lane + 32) * GG);
            float v2 = (lane < 21) ? __ldg(base + (long)(lane + 64) * GG) : 0.0f;

            // lane-parallel dedup: any kept pair with lower n mapping to same cell?
            bool notfirst = false;
            for (int m2b = 0; m2b < n; m2b += 32) {
                int m2 = m2b + lane;
                bool m = false;
                if (m2 < n)
                    m = skeep[a * NT + m2] && (sbi[m2] == b) &&
                        (sgi[m2] == gi) && (sgj[m2] == gj);
                if (__any_sync(0xFFFFFFFF, m)) { notfirst = true; break; }
            }

            // cls BCE contributions
            const int cls = scls[n];
            float csum = 0.0f;
            if (lane >= 5) csum += softplusf(v0) - ((lane - 5 == cls) ? v0 : 0.0f);
            csum += softplusf(v1) - ((lane + 27 == cls) ? v1 : 0.0f);
            if (lane < 21) csum += softplusf(v2) - ((lane + 59 == cls) ? v2 : 0.0f);
            #pragma unroll
            for (int o = 16; o > 0; o >>= 1)
                csum += __shfl_down_sync(0xFFFFFFFF, csum, o);

            // broadcast box channels
            float obj = __shfl_sync(0xFFFFFFFF, v0, 0);
            float px  = __shfl_sync(0xFFFFFFFF, v0, 1);
            float py  = __shfl_sync(0xFFFFFFFF, v0, 2);
            float pw  = __shfl_sync(0xFFFFFFFF, v0, 3);
            float ph  = __shfl_sync(0xFFFFFFFF, v0, 4);

            if (lane == 0) {
                float pcx = sigmoidf(px) + (float)gi;
                float pcy = sigmoidf(py) + (float)gj;
                float aw = c_anchors[s][a][0] / stride;
                float ah = c_anchors[s][a][1] / stride;
                float pbw = __expf(fminf(fmaxf(pw, -4.0f), 4.0f)) * aw;
                float pbh = __expf(fminf(fmaxf(ph, -4.0f), 4.0f)) * ah;

                float b1x0 = (pcx - pbw * 0.5f) * stride;
                float b1y0 = (pcy - pbh * 0.5f) * stride;
                float b1x1 = (pcx + pbw * 0.5f) * stride;
                float b1y1 = (pcy + pbh * 0.5f) * stride;

                float tcx = scx[n], tcy = scy[n];
                float tgw = sgw[n], tgh = sgh[n];
                float b2x0 = (tcx - tgw * 0.5f) * stride;
                float b2y0 = (tcy - tgh * 0.5f) * stride;
                float b2x1 = (tcx + tgw * 0.5f) * stride;
                float b2y1 = (tcy + tgh * 0.5f) * stride;

                const float eps = 1e-7f;
                float w1 = b1x1 - b1x0, h1 = b1y1 - b1y0;
                float w2 = b2x1 - b2x0, h2 = b2y1 - b2y0;
                float ix = fmaxf(fminf(b1x1, b2x1) - fmaxf(b1x0, b2x0), 0.0f);
                float iy = fmaxf(fminf(b1y1, b2y1) - fmaxf(b1y0, b2y0), 0.0f);
                float inter = ix * iy;
                float uni = w1 * h1 + w2 * h2 - inter + eps;
                float iou = inter / uni;
                float cw = fmaxf(b1x1, b2x1) - fminf(b1x0, b2x0);
                float ch = fmaxf(b1y1, b2y1) - fminf(b1y0, b2y0);
                float c2 = cw * cw + ch * ch + eps;
                float dx = b2x0 + b2x1 - b1x0 - b1x1;
                float dy = b2y0 + b2y1 - b1y0 - b1y1;
                float rho2 = (dx * dx + dy * dy) * 0.25f;
                const float k4pi2 = 4.0f / (float)(M_PI * M_PI);
                float da = atanf(w2 / (h2 + eps)) - atanf(w1 / (h1 + eps));
                float v = k4pi2 * da * da;
                float alpha = v / (v - iou + (1.0f + eps));
                float ciou = iou - (rho2 / c2 + v * alpha);

                atomicAdd(&sacc[0], 1.0);
                atomicAdd(&sacc[1], (double)(1.0f - ciou));
                atomicAdd(&sacc[2], (double)csum);
                if (!notfirst) atomicAdd(&sacc[3], (double)obj);
            }
        }
        __syncthreads();
        if (tid == 0) {
            atomicAdd(&g_nkeep[s],  sacc[0]);
            atomicAdd(&g_box[s],    sacc[1]);
            atomicAdd(&g_cls[s],    sacc[2]);
            atomicAdd(&g_objsub[s], sacc[3]);
        }
    } else {
        // =============== OBJ BLOCKS ===============
        __syncthreads();   // pair with init of ssp
        int i = (bx - PAIR_BLOCKS) * BLOCK + tid;
        if (i < OBJ_TOTAL4) {
            int s, j;
            if (i < 76800)      { s = 0; j = i; }
            else if (i < 96000) { s = 1; j = i - 76800; }
            else                { s = 2; j = i - 96000; }
            const float* pred = (s == 0) ? p0 : ((s == 1) ? p1 : p2);
            const int GG = c_G[s] * c_G[s];
            int idx = j << 2;
            int plane = idx / GG;
            int w = idx - plane * GG;
            int b = plane / 3;
            int a = plane - b * 3;
            const float4 v = *(const float4*)(pred + ((long)b * 255 + (long)a * 85) * GG + w);
            double val = (double)(softplusf(v.x) + softplusf(v.y) +
                                  softplusf(v.z) + softplusf(v.w));
            atomicAdd(&ssp[s], val);
        }
        __syncthreads();
        if (tid < 3) atomicAdd(&g_sp[tid], ssp[tid]);
    }

    // =============== COMPLETION / FINALIZE ===============
    if (tid == 0) {
        __threadfence();
        unsigned int old = atomicAdd(&g_done, 1);
        if (old == TOTAL_BLOCKS - 1) {
            double tot = 0.0;
            #pragma unroll
            for (int s = 0; s < 3; s++) {
                double M  = (double)BB * 3.0 * (double)c_G[s] * (double)c_G[s];
                double nk = fmax(atomic_read(&g_nkeep[s]), 1.0);
                double lb = atomic_read(&g_box[s]) / nk;
                double lo = (atomic_read(&g_sp[s]) - atomic_read(&g_objsub[s])) / M;
                double lc = atomic_read(&g_cls[s]) / (nk * (double)NCC);
                tot += 0.05 * lb + 1.0 * lo + 0.5 * lc;
            }
            out[0] = (float)tot;
            // reset state for next graph replay (deterministic)
            #pragma unroll
            for (int s = 0; s < 3; s++) {
                g_sp[s] = 0.0; g_objsub[s] = 0.0; g_box[s] = 0.0;
                g_cls[s] = 0.0; g_nkeep[s] = 0.0;
            }
            g_done = 0;
            __threadfence();
        }
    }
}

extern "C" void kernel_launch(void* const* d_in, const int* in_sizes, int n_in,
                              void* d_out, int out_size)
{
    const float* p0  = (const float*)d_in[0];
    const float* p1  = (const float*)d_in[1];
    const float* p2  = (const float*)d_in[2];
    const float* tgt = (const float*)d_in[3];
    float* out = (float*)d_out;

    fused_loss_kernel<<<TOTAL_BLOCKS, BLOCK>>>(p0, p1, p2, tgt, out);
}

// round 6
// speedup vs baseline: 3.0075x; 1.5579x over previous
#include <cuda_runtime.h>
#include <math.h>

#define NT   300
#define NCC  80
#define IMGS 640.0f

#define PAIR_BLOCKS_PER_SCALE 15   // 15 blocks * 16 warps * 4 pairs = 960 >= 900
#define PAIR_BLOCKS 45
#define OBJ_BLOCKS  99             // s0:75, s1:19, s2:5 (1024 float4 per block)
#define TOTAL_BLOCKS 144
#define BLOCK 512

// accumulators: [0..2]=sp  [3..5]=objsub  [6..8]=box  [9..11]=cls  [12..14]=nkeep
__device__ double g_acc[16] = {0};
__device__ unsigned int g_done = 0;

__constant__ float c_anchors[3][3][2] = {
    {{10.f,13.f},{16.f,30.f},{33.f,23.f}},
    {{30.f,61.f},{62.f,45.f},{59.f,119.f}},
    {{116.f,90.f},{156.f,198.f},{373.f,326.f}}
};
__constant__ float c_stride[3] = {8.f, 16.f, 32.f};
__constant__ int   c_G[3]      = {80, 40, 20};

__device__ __forceinline__ float sigmoidf(float x) {
    return 1.0f / (1.0f + __expf(-x));
}
// sum of softplus over a float4, one log for four elements:
// softplus(x) = max(x,0) + ln(1 + e^{-|x|})
__device__ __forceinline__ float sp4(const float4 v) {
    float m = fmaxf(v.x, 0.f) + fmaxf(v.y, 0.f) + fmaxf(v.z, 0.f) + fmaxf(v.w, 0.f);
    float pr = (1.f + __expf(-fabsf(v.x))) * (1.f + __expf(-fabsf(v.y)))
             * (1.f + __expf(-fabsf(v.z))) * (1.f + __expf(-fabsf(v.w)));
    return m + __logf(pr);
}

template<int GG4>
__device__ __forceinline__ float obj_thread(const float* __restrict__ pred, int j) {
    int plane = j / GG4;              // compile-time divisor -> mulhi
    int w4 = j - plane * GG4;
    const float4 v = *(const float4*)(pred + (long)plane * (340 * GG4) + 4 * w4);
    return sp4(v);
}

__global__ void __launch_bounds__(BLOCK)
fused_loss_kernel(const float* __restrict__ p0,
                  const float* __restrict__ p1,
                  const float* __restrict__ p2,
                  const float* __restrict__ tgt,
                  float* __restrict__ out)
{
    const int tid = threadIdx.x;
    const int bx  = blockIdx.x;
    const int warp = tid >> 5, lane = tid & 31;

    if (bx < PAIR_BLOCKS) {
        // ======================= PAIR BLOCKS =======================
        __shared__ float scx[NT], scy[NT], sgw[NT], sgh[NT];
        __shared__ int   sbi[NT], scls[NT], sgi[NT], sgj[NT];
        __shared__ unsigned char skeep[3 * NT];
        __shared__ double sacc[4];   // nkeep, box, cls, objsub

        const int s    = bx / PAIR_BLOCKS_PER_SCALE;
        const int slot = bx - s * PAIR_BLOCKS_PER_SCALE;
        const float* pred = (s == 0) ? p0 : ((s == 1) ? p1 : p2);
        const int   G  = c_G[s];
        const int   GG = G * G;
        const float stride = c_stride[s];

        if (tid < 4) sacc[tid] = 0.0;

        for (int n = tid; n < NT; n += BLOCK) {
            float bi = tgt[n * 6 + 0];
            float cl = tgt[n * 6 + 1];
            float tx = tgt[n * 6 + 2];
            float ty = tgt[n * 6 + 3];
            float tw = tgt[n * 6 + 4];
            float th = tgt[n * 6 + 5];
            float cx = tx * (float)G;
            float cy = ty * (float)G;
            int gi = (int)cx; gi = min(max(gi, 0), G - 1);
            int gj = (int)cy; gj = min(max(gj, 0), G - 1);
            scx[n] = cx; scy[n] = cy;
            sgw[n] = tw * (float)G; sgh[n] = th * (float)G;
            sbi[n] = (int)bi; scls[n] = (int)cl;
            sgi[n] = gi; sgj[n] = gj;
            float gw = tw * IMGS, gh = th * IMGS;
            #pragma unroll
            for (int a = 0; a < 3; a++) {
                float rw = gw / c_anchors[s][a][0];
                float rh = gh / c_anchors[s][a][1];
                float m = fmaxf(fmaxf(rw, 1.0f / fmaxf(rw, 1e-8f)),
                                fmaxf(rh, 1.0f / fmaxf(rh, 1e-8f)));
                skeep[a * NT + n] = (m < 4.0f) ? 1 : 0;
            }
        }
        __syncthreads();

        float w_kf = 0.f, w_box = 0.f, w_cls = 0.f, w_sub = 0.f;

        #pragma unroll
        for (int k = 0; k < 4; k++) {
            const int t = slot * 64 + warp * 4 + k;       // pair id
            if (t >= 3 * NT) continue;
            if (!skeep[t]) continue;                       // warp-uniform

            const int a = t / NT, n = t - a * NT;
            const int b  = sbi[n];
            const int gi = sgi[n];
            const int gj = sgj[n];
            const float* base = pred + ((long)b * 255 + (long)a * 85) * GG
                                     + (long)gj * G + gi;

            float v0 = __ldg(base + (long)lane * GG);
            float v1 = __ldg(base + (long)(lane + 32) * GG);
            float v2 = (lane < 21) ? __ldg(base + (long)(lane + 64) * GG) : 0.0f;

            // lane-parallel dedup: first kept pair mapping to this cell wins
            bool notfirst = false;
            for (int m2b = 0; m2b < n; m2b += 32) {
                int m2 = m2b + lane;
                bool m = false;
                if (m2 < n)
                    m = skeep[a * NT + m2] && (sbi[m2] == b) &&
                        (sgi[m2] == gi) && (sgj[m2] == gj);
                if (__any_sync(0xFFFFFFFF, m)) { notfirst = true; break; }
            }

            // cls BCE: per-lane products + one log
            const int cls = scls[n];
            float mx = 0.f, pr = 1.f, sub = 0.f;
            if (lane >= 5) {
                mx += fmaxf(v0, 0.f);
                pr *= (1.f + __expf(-fabsf(v0)));
                if (lane - 5 == cls) sub += v0;
            }
            mx += fmaxf(v1, 0.f);
            pr *= (1.f + __expf(-fabsf(v1)));
            if (lane + 27 == cls) sub += v1;
            if (lane < 21) {
                mx += fmaxf(v2, 0.f);
                pr *= (1.f + __expf(-fabsf(v2)));
                if (lane + 59 == cls) sub += v2;
            }
            float csum = mx + __logf(pr) - sub;
            #pragma unroll
            for (int o = 16; o > 0; o >>= 1)
                csum += __shfl_down_sync(0xFFFFFFFF, csum, o);

            float obj = __shfl_sync(0xFFFFFFFF, v0, 0);
            float px  = __shfl_sync(0xFFFFFFFF, v0, 1);
            float py  = __shfl_sync(0xFFFFFFFF, v0, 2);
            float pw  = __shfl_sync(0xFFFFFFFF, v0, 3);
            float ph  = __shfl_sync(0xFFFFFFFF, v0, 4);

            if (lane == 0) {
                float pcx = sigmoidf(px) + (float)gi;
                float pcy = sigmoidf(py) + (float)gj;
                float aw = c_anchors[s][a][0] / stride;
                float ah = c_anchors[s][a][1] / stride;
                float pbw = __expf(fminf(fmaxf(pw, -4.0f), 4.0f)) * aw;
                float pbh = __expf(fminf(fmaxf(ph, -4.0f), 4.0f)) * ah;

                float b1x0 = (pcx - pbw * 0.5f) * stride;
                float b1y0 = (pcy - pbh * 0.5f) * stride;
                float b1x1 = (pcx + pbw * 0.5f) * stride;
                float b1y1 = (pcy + pbh * 0.5f) * stride;

                float tcx = scx[n], tcy = scy[n];
                float tgw = sgw[n], tgh = sgh[n];
                float b2x0 = (tcx - tgw * 0.5f) * stride;
                float b2y0 = (tcy - tgh * 0.5f) * stride;
                float b2x1 = (tcx + tgw * 0.5f) * stride;
                float b2y1 = (tcy + tgh * 0.5f) * stride;

                const float eps = 1e-7f;
                float w1 = b1x1 - b1x0, h1 = b1y1 - b1y0;
                float w2 = b2x1 - b2x0, h2 = b2y1 - b2y0;
                float ix = fmaxf(fminf(b1x1, b2x1) - fmaxf(b1x0, b2x0), 0.0f);
                float iy = fmaxf(fminf(b1y1, b2y1) - fmaxf(b1y0, b2y0), 0.0f);
                float inter = ix * iy;
                float uni = w1 * h1 + w2 * h2 - inter + eps;
                float iou = inter / uni;
                float cw = fmaxf(b1x1, b2x1) - fminf(b1x0, b2x0);
                float ch = fmaxf(b1y1, b2y1) - fminf(b1y0, b2y0);
                float c2 = cw * cw + ch * ch + eps;
                float dx = b2x0 + b2x1 - b1x0 - b1x1;
                float dy = b2y0 + b2y1 - b1y0 - b1y1;
                float rho2 = (dx * dx + dy * dy) * 0.25f;
                const float k4pi2 = 4.0f / (float)(M_PI * M_PI);
                float da = atanf(w2 / (h2 + eps)) - atanf(w1 / (h1 + eps));
                float v = k4pi2 * da * da;
                float alpha = v / (v - iou + (1.0f + eps));
                float ciou = iou - (rho2 / c2 + v * alpha);

                w_kf  += 1.0f;
                w_box += (1.0f - ciou);
                w_cls += csum;
                if (!notfirst) w_sub += obj;
            }
        }

        if (lane == 0 && w_kf > 0.f) {
            atomicAdd(&sacc[0], (double)w_kf);
            atomicAdd(&sacc[1], (double)w_box);
            atomicAdd(&sacc[2], (double)w_cls);
            if (w_sub != 0.f) atomicAdd(&sacc[3], (double)w_sub);
        }
        __syncthreads();
        // tid0 performs ALL global adds; its later __threadfence orders them
        // before the g_done increment (single-thread program order).
        if (tid == 0) {
            atomicAdd(&g_acc[12 + s], sacc[0]);
            atomicAdd(&g_acc[6 + s],  sacc[1]);
            atomicAdd(&g_acc[9 + s],  sacc[2]);
            atomicAdd(&g_acc[3 + s],  sacc[3]);
        }
    } else {
        // ======================= OBJ BLOCKS =======================
        __shared__ double ssp;
        if (tid == 0) ssp = 0.0;
        __syncthreads();

        const int ob = bx - PAIR_BLOCKS;
        int s;
        float acc = 0.f;
        if (ob < 75) {
            s = 0;
            int j = ob * 1024 + tid;
            acc += obj_thread<1600>(p0, j);
            acc += obj_thread<1600>(p0, j + 512);
        } else if (ob < 94) {
            s = 1;
            int j = (ob - 75) * 1024 + tid;
            if (j < 19200)       acc += obj_thread<400>(p1, j);
            if (j + 512 < 19200) acc += obj_thread<400>(p1, j + 512);
        } else {
            s = 2;
            int j = (ob - 94) * 1024 + tid;
            if (j < 4800)        acc += obj_thread<100>(p2, j);
            if (j + 512 < 4800)  acc += obj_thread<100>(p2, j + 512);
        }

        #pragma unroll
        for (int o = 16; o > 0; o >>= 1)
            acc += __shfl_down_sync(0xFFFFFFFF, acc, o);
        if (lane == 0) atomicAdd(&ssp, (double)acc);
        __syncthreads();
        if (tid == 0) atomicAdd(&g_acc[s], ssp);
    }

    // ======================= FINALIZE =======================
    if (tid == 0) {
        __threadfence();
        unsigned int old = atomicAdd(&g_done, 1);
        if (old == TOTAL_BLOCKS - 1) {
            volatile double* A = g_acc;
            double tot = 0.0;
            #pragma unroll
            for (int s2 = 0; s2 < 3; s2++) {
                double G2 = (double)c_G[s2] * (double)c_G[s2];
                double M  = 48.0 * G2;
                double nk = fmax(A[12 + s2], 1.0);
                double lb = A[6 + s2] / nk;
                double lo = (A[s2] - A[3 + s2]) / M;
                double lc = A[9 + s2] / (nk * (double)NCC);
                tot += 0.05 * lb + 1.0 * lo + 0.5 * lc;
            }
            out[0] = (float)tot;
            #pragma unroll
            for (int i = 0; i < 16; i++) g_acc[i] = 0.0;
            g_done = 0;
            __threadfence();
        }
    }
}

extern "C" void kernel_launch(void* const* d_in, const int* in_sizes, int n_in,
                              void* d_out, int out_size)
{
    const float* p0  = (const float*)d_in[0];
    const float* p1  = (const float*)d_in[1];
    const float* p2  = (const float*)d_in[2];
    const float* tgt = (const float*)d_in[3];
    float* out = (float*)d_out;

    fused_loss_kernel<<<TOTAL_BLOCKS, BLOCK>>>(p0, p1, p2, tgt, out);
}

// round 7
// speedup vs baseline: 3.4014x; 1.1310x over previous
#include <cuda_runtime.h>
#include <math.h>

#define NT   300
#define NCC  80
#define IMGS 640.0f

#define PAIR_BLOCKS 113            // 113 blocks * 8 warps * 1 pair = 904 >= 900
#define OBJ_BLOCKS  34             // s0:25, s1:7, s2:2 (3072 float4 per block)
#define TOTAL_BLOCKS 147
#define BLOCK 256

// accumulators: [0..2]=sp  [3..5]=objsub  [6..8]=box  [9..11]=cls  [12..14]=nkeep
__device__ double g_acc[16] = {0};
__device__ unsigned int g_done = 0;

__constant__ float c_anchors[3][3][2] = {
    {{10.f,13.f},{16.f,30.f},{33.f,23.f}},
    {{30.f,61.f},{62.f,45.f},{59.f,119.f}},
    {{116.f,90.f},{156.f,198.f},{373.f,326.f}}
};
__constant__ float c_stride[3] = {8.f, 16.f, 32.f};
__constant__ int   c_G[3]      = {80, 40, 20};

__device__ __forceinline__ float sigmoidf(float x) {
    return 1.0f / (1.0f + __expf(-x));
}
// sum of softplus over a float4, one log for four elements:
// softplus(x) = max(x,0) + ln(1 + e^{-|x|})
__device__ __forceinline__ float sp4(const float4 v) {
    float m = fmaxf(v.x, 0.f) + fmaxf(v.y, 0.f) + fmaxf(v.z, 0.f) + fmaxf(v.w, 0.f);
    float pr = (1.f + __expf(-fabsf(v.x))) * (1.f + __expf(-fabsf(v.y)))
             * (1.f + __expf(-fabsf(v.z))) * (1.f + __expf(-fabsf(v.w)));
    return m + __logf(pr);
}

template<int GG4>
__device__ __forceinline__ float obj_thread(const float* __restrict__ pred, int j) {
    int plane = j / GG4;              // compile-time divisor -> mulhi
    int w4 = j - plane * GG4;
    const float4 v = *(const float4*)(pred + (long)plane * (340 * GG4) + 4 * w4);
    return sp4(v);
}

__global__ void __launch_bounds__(BLOCK)
fused_loss_kernel(const float* __restrict__ p0,
                  const float* __restrict__ p1,
                  const float* __restrict__ p2,
                  const float* __restrict__ tgt,
                  float* __restrict__ out)
{
    const int tid = threadIdx.x;
    const int bx  = blockIdx.x;
    const int warp = tid >> 5, lane = tid & 31;

    if (bx < PAIR_BLOCKS) {
        // ======================= PAIR BLOCKS (1 pair / warp) =======================
        __shared__ float scx[NT], scy[NT], sgw[NT], sgh[NT];
        __shared__ int   sbi[NT], scls[NT], sgi[NT], sgj[NT];
        __shared__ unsigned char skeep[3 * NT];
        __shared__ double sacc[4];   // nkeep, box, cls, objsub

        if (tid < 4) sacc[tid] = 0.0;

        const int t = bx * 8 + warp;          // pair id in [0, 904)
        const int s = (t < NT) ? 0 : ((t < 2 * NT) ? 0 : 0); // placeholder (s from t below)
        // pair id layout: t = a*NT + n within ONE scale? No — pairs span scales:
        // global pair id: scale = t / 900? We use: scale chosen by t / 300 % ... 
        // Simpler: t in [0,900): sc = t / 300 gives WRONG split (need 3 anchors per scale).
        // Layout: t = sc*300 + n would only give 1 anchor. Use t in [0,2700)? No:
        // we process per-scale pairs: total pairs = 3 scales * 3 anchors * 300 = 2700.
        (void)s;

        // Actually enumerate all 2700 (scale,anchor,target) pairs: 113*8=904 warps
        // handle 3 pairs each (one per scale) to keep staging shared across scales.
        // -> stage targets + keep for ALL scales, each warp does pair index p = t
        //    for each scale with anchor a = p/300, n = p%300.

        for (int n = tid; n < NT; n += BLOCK) {
            float bi = tgt[n * 6 + 0];
            float cl = tgt[n * 6 + 1];
            float tx = tgt[n * 6 + 2];
            float ty = tgt[n * 6 + 3];
            float tw = tgt[n * 6 + 4];
            float th = tgt[n * 6 + 5];
            sbi[n] = (int)bi; scls[n] = (int)cl;
            scx[n] = tx; scy[n] = ty;          // store normalized; scale per-s later
            sgw[n] = tw; sgh[n] = th;
            // keep flags are scale-dependent; store compactly: bit a of byte s? 
            // We stage keep for all 3 scales * 3 anchors = 9 bits -> use 3 bytes rows.
            float gw = tw * IMGS, gh = th * IMGS;
            #pragma unroll
            for (int sc = 0; sc < 3; sc++) {
                unsigned char bits = 0;
                #pragma unroll
                for (int a = 0; a < 3; a++) {
                    float rw = gw / c_anchors[sc][a][0];
                    float rh = gh / c_anchors[sc][a][1];
                    float m = fmaxf(fmaxf(rw, 1.0f / fmaxf(rw, 1e-8f)),
                                    fmaxf(rh, 1.0f / fmaxf(rh, 1e-8f)));
                    if (m < 4.0f) bits |= (1 << a);
                }
                skeep[sc * NT + n] = bits;
            }
        }
        __syncthreads();

        float w_kf = 0.f, w_box = 0.f, w_cls = 0.f, w_sub = 0.f;

        const int p = bx * 8 + warp;          // [0, 904): (anchor,target) index
        if (p < 3 * NT) {
            const int a = p / NT, n = p - a * NT;
            const int b   = sbi[n];
            const int cls = scls[n];

            #pragma unroll
            for (int sc = 0; sc < 3; sc++) {
                if (!(skeep[sc * NT + n] & (1 << a))) continue;  // warp-uniform

                const float* pred = (sc == 0) ? p0 : ((sc == 1) ? p1 : p2);
                const int   G  = c_G[sc];
                const int   GG = G * G;
                const float stride = c_stride[sc];

                float cx = scx[n] * (float)G;
                float cy = scy[n] * (float)G;
                int gi = (int)cx; gi = min(max(gi, 0), G - 1);
                int gj = (int)cy; gj = min(max(gj, 0), G - 1);

                const float* base = pred + ((long)b * 255 + (long)a * 85) * GG
                                         + (long)gj * G + gi;

                float v0 = __ldg(base + (long)lane * GG);
                float v1 = __ldg(base + (long)(lane + 32) * GG);
                float v2 = (lane < 21) ? __ldg(base + (long)(lane + 64) * GG) : 0.0f;

                // lane-parallel dedup: first kept pair mapping to this cell wins.
                // Cell key depends on (b, gi, gj) which is scale-dependent via gi,gj.
                bool notfirst = false;
                for (int m2b = 0; m2b < n; m2b += 32) {
                    int m2 = m2b + lane;
                    bool m = false;
                    if (m2 < n && (skeep[sc * NT + m2] & (1 << a)) && sbi[m2] == b) {
                        float mcx = scx[m2] * (float)G;
                        float mcy = scy[m2] * (float)G;
                        int mgi = (int)mcx; mgi = min(max(mgi, 0), G - 1);
                        int mgj = (int)mcy; mgj = min(max(mgj, 0), G - 1);
                        m = (mgi == gi) && (mgj == gj);
                    }
                    if (__any_sync(0xFFFFFFFF, m)) { notfirst = true; break; }
                }

                // cls BCE: per-lane products + one log
                float mx = 0.f, pr = 1.f, sub = 0.f;
                if (lane >= 5) {
                    mx += fmaxf(v0, 0.f);
                    pr *= (1.f + __expf(-fabsf(v0)));
                    if (lane - 5 == cls) sub += v0;
                }
                mx += fmaxf(v1, 0.f);
                pr *= (1.f + __expf(-fabsf(v1)));
                if (lane + 27 == cls) sub += v1;
                if (lane < 21) {
                    mx += fmaxf(v2, 0.f);
                    pr *= (1.f + __expf(-fabsf(v2)));
                    if (lane + 59 == cls) sub += v2;
                }
                float csum = mx + __logf(pr) - sub;
                #pragma unroll
                for (int o = 16; o > 0; o >>= 1)
                    csum += __shfl_down_sync(0xFFFFFFFF, csum, o);

                float obj = __shfl_sync(0xFFFFFFFF, v0, 0);
                float px  = __shfl_sync(0xFFFFFFFF, v0, 1);
                float py  = __shfl_sync(0xFFFFFFFF, v0, 2);
                float pw  = __shfl_sync(0xFFFFFFFF, v0, 3);
                float ph  = __shfl_sync(0xFFFFFFFF, v0, 4);

                if (lane == 0) {
                    float pcx = sigmoidf(px) + (float)gi;
                    float pcy = sigmoidf(py) + (float)gj;
                    float aw = c_anchors[sc][a][0] / stride;
                    float ah = c_anchors[sc][a][1] / stride;
                    float pbw = __expf(fminf(fmaxf(pw, -4.0f), 4.0f)) * aw;
                    float pbh = __expf(fminf(fmaxf(ph, -4.0f), 4.0f)) * ah;

                    float b1x0 = (pcx - pbw * 0.5f) * stride;
                    float b1y0 = (pcy - pbh * 0.5f) * stride;
                    float b1x1 = (pcx + pbw * 0.5f) * stride;
                    float b1y1 = (pcy + pbh * 0.5f) * stride;

                    float tgw = sgw[n] * (float)G;
                    float tgh = sgh[n] * (float)G;
                    float b2x0 = (cx - tgw * 0.5f) * stride;
                    float b2y0 = (cy - tgh * 0.5f) * stride;
                    float b2x1 = (cx + tgw * 0.5f) * stride;
                    float b2y1 = (cy + tgh * 0.5f) * stride;

                    const float eps = 1e-7f;
                    float w1 = b1x1 - b1x0, h1 = b1y1 - b1y0;
                    float w2 = b2x1 - b2x0, h2 = b2y1 - b2y0;
                    float ix = fmaxf(fminf(b1x1, b2x1) - fmaxf(b1x0, b2x0), 0.0f);
                    float iy = fmaxf(fminf(b1y1, b2y1) - fmaxf(b1y0, b2y0), 0.0f);
                    float inter = ix * iy;
                    float uni = w1 * h1 + w2 * h2 - inter + eps;
                    float iou = inter / uni;
                    float cw = fmaxf(b1x1, b2x1) - fminf(b1x0, b2x0);
                    float ch = fmaxf(b1y1, b2y1) - fminf(b1y0, b2y0);
                    float c2 = cw * cw + ch * ch + eps;
                    float dx = b2x0 + b2x1 - b1x0 - b1x1;
                    float dy = b2y0 + b2y1 - b1y0 - b1y1;
                    float rho2 = (dx * dx + dy * dy) * 0.25f;
                    const float k4pi2 = 4.0f / (float)(M_PI * M_PI);
                    float da = atanf(w2 / (h2 + eps)) - atanf(w1 / (h1 + eps));
                    float v = k4pi2 * da * da;
                    float alpha = v / (v - iou + (1.0f + eps));
                    float ciou = iou - (rho2 / c2 + v * alpha);

                    // accumulate per-scale directly to shared? need per-scale slots.
                    // use local then shared per-scale atomics below
                    w_kf  = 1.0f; w_box = 1.0f - ciou; w_cls = csum;
                    w_sub = notfirst ? 0.f : obj;

                    atomicAdd(&sacc[0], 0.0);  // no-op placeholder removed below
                }
                // per-scale accumulation must go to per-scale global slots:
                if (lane == 0) {
                    atomicAdd(&g_acc[12 + sc], (double)w_kf);
                    atomicAdd(&g_acc[6 + sc],  (double)w_box);
                    atomicAdd(&g_acc[9 + sc],  (double)w_cls);
                    if (w_sub != 0.f) atomicAdd(&g_acc[3 + sc], (double)w_sub);
                    w_kf = w_box = w_cls = w_sub = 0.f;
                }
            }
        }
        // ensure this block's warp-level global atomics are complete before
        // signalling g_done: issue a dummy dependent read via syncthreads +
        // rely on tid0 threadfence ordering its OWN later atomic; for other
        // warps' atomics we force completion by using atomicAdd return values
        // implicitly? -> Use __threadfence per lane0 BEFORE syncthreads:
        __threadfence();
        __syncthreads();
    } else {
        // ======================= OBJ BLOCKS =======================
        __shared__ double ssp;
        if (tid == 0) ssp = 0.0;
        __syncthreads();

        const int ob = bx - PAIR_BLOCKS;
        int s;
        float acc = 0.f;
        if (ob < 25) {
            s = 0;
            int j = ob * 3072 + tid;
            #pragma unroll
            for (int k = 0; k < 12; k++)
                acc += obj_thread<1600>(p0, j + k * BLOCK);
        } else if (ob < 32) {
            s = 1;
            int j = (ob - 25) * 3072 + tid;
            #pragma unroll
            for (int k = 0; k < 12; k++)
                if (j + k * BLOCK < 19200) acc += obj_thread<400>(p1, j + k * BLOCK);
        } else {
            s = 2;
            int j = (ob - 32) * 3072 + tid;
            #pragma unroll
            for (int k = 0; k < 12; k++)
                if (j + k * BLOCK < 4800) acc += obj_thread<100>(p2, j + k * BLOCK);
        }

        #pragma unroll
        for (int o = 16; o > 0; o >>= 1)
            acc += __shfl_down_sync(0xFFFFFFFF, acc, o);
        if (lane == 0) atomicAdd(&ssp, (double)acc);
        __syncthreads();
        if (tid == 0) atomicAdd(&g_acc[s], ssp);
        __threadfence();
        __syncthreads();
    }

    // ======================= FINALIZE =======================
    if (tid == 0) {
        __threadfence();
        unsigned int old = atomicAdd(&g_done, 1);
        if (old == TOTAL_BLOCKS - 1) {
            volatile double* A = g_acc;
            double tot = 0.0;
            #pragma unroll
            for (int s2 = 0; s2 < 3; s2++) {
                double G2 = (double)c_G[s2] * (double)c_G[s2];
                double M  = 48.0 * G2;
                double nk = fmax(A[12 + s2], 1.0);
                double lb = A[6 + s2] / nk;
                double lo = (A[s2] - A[3 + s2]) / M;
                double lc = A[9 + s2] / (nk * (double)NCC);
                tot += 0.05 * lb + 1.0 * lo + 0.5 * lc;
            }
            out[0] = (float)tot;
            #pragma unroll
            for (int i = 0; i < 16; i++) g_acc[i] = 0.0;
            g_done = 0;
            __threadfence();
        }
    }
}

extern "C" void kernel_launch(void* const* d_in, const int* in_sizes, int n_in,
                              void* d_out, int out_size)
{
    const float* p0  = (const float*)d_in[0];
    const float* p1  = (const float*)d_in[1];
    const float* p2  = (const float*)d_in[2];
    const float* tgt = (const float*)d_in[3];
    float* out = (float*)d_out;

    fused_loss_kernel<<<TOTAL_BLOCKS, BLOCK>>>(p0, p1, p2, tgt, out);
}

// round 9
// speedup vs baseline: 3.4542x; 1.0155x over previous
#include <cuda_runtime.h>
#include <math.h>

#define NT   300
#define NCC  80
#define IMGS 640.0f

#define TOTAL_BLOCKS 147
#define BLOCK 256
#define OBJ_TOTAL4 100800          // float4 count across all obj channels
#define OBJ_STRIDE (TOTAL_BLOCKS * BLOCK)   // 37632

// accumulators: [0..2]=sp  [3..5]=objsub  [6..8]=box  [9..11]=cls  [12..14]=nkeep
__device__ double g_acc[16] = {0};
__device__ unsigned int g_done = 0;

__constant__ float c_anchors[3][3][2] = {
    {{10.f,13.f},{16.f,30.f},{33.f,23.f}},
    {{30.f,61.f},{62.f,45.f},{59.f,119.f}},
    {{116.f,90.f},{156.f,198.f},{373.f,326.f}}
};
__constant__ float c_ranchors[3][3][2] = {   // reciprocals (constant expressions)
    {{1.f/10.f,1.f/13.f},{1.f/16.f,1.f/30.f},{1.f/33.f,1.f/23.f}},
    {{1.f/30.f,1.f/61.f},{1.f/62.f,1.f/45.f},{1.f/59.f,1.f/119.f}},
    {{1.f/116.f,1.f/90.f},{1.f/156.f,1.f/198.f},{1.f/373.f,1.f/326.f}}
};
__constant__ float c_stride[3] = {8.f, 16.f, 32.f};
__constant__ int   c_G[3]      = {80, 40, 20};

__device__ __forceinline__ float sigmoidf(float x) {
    return 1.0f / (1.0f + __expf(-x));
}
// sum of softplus over a float4, one log for four elements
__device__ __forceinline__ float sp4(const float4 v) {
    float m = fmaxf(v.x, 0.f) + fmaxf(v.y, 0.f) + fmaxf(v.z, 0.f) + fmaxf(v.w, 0.f);
    float pr = (1.f + __expf(-fabsf(v.x))) * (1.f + __expf(-fabsf(v.y)))
             * (1.f + __expf(-fabsf(v.z))) * (1.f + __expf(-fabsf(v.w)));
    return m + __logf(pr);
}

template<int GG4>
__device__ __forceinline__ float obj_elem(const float* __restrict__ pred, int j) {
    int plane = j / GG4;              // compile-time divisor
    int w4 = j - plane * GG4;
    const float4 v = *(const float4*)(pred + (long)plane * (340 * GG4) + 4 * w4);
    return sp4(v);
}

__global__ void __launch_bounds__(BLOCK)
fused_loss_kernel(const float* __restrict__ p0,
                  const float* __restrict__ p1,
                  const float* __restrict__ p2,
                  const float* __restrict__ tgt,
                  float* __restrict__ out)
{
    const int tid  = threadIdx.x;
    const int bx   = blockIdx.x;
    const int warp = tid >> 5, lane = tid & 31;

    __shared__ float  scx[NT], scy[NT], sgw[NT], sgh[NT];   // normalized
    __shared__ short  sbi[NT], scls[NT];
    __shared__ unsigned char sgi[3][NT], sgj[3][NT];
    __shared__ unsigned short skeep[NT];                     // 9 bits: sc*3+a
    __shared__ double sacc[15];

    if (tid < 15) sacc[tid] = 0.0;

    // ---------------- Phase 0: stage targets ----------------
    for (int n = tid; n < NT; n += BLOCK) {
        float bi = tgt[n * 6 + 0];
        float cl = tgt[n * 6 + 1];
        float tx = tgt[n * 6 + 2];
        float ty = tgt[n * 6 + 3];
        float tw = tgt[n * 6 + 4];
        float th = tgt[n * 6 + 5];
        sbi[n] = (short)bi; scls[n] = (short)cl;
        scx[n] = tx; scy[n] = ty; sgw[n] = tw; sgh[n] = th;
        float gw = tw * IMGS, gh = th * IMGS;
        unsigned bits = 0;
        #pragma unroll
        for (int sc = 0; sc < 3; sc++) {
            const int G = c_G[sc];
            int gi = (int)(tx * (float)G); gi = min(max(gi, 0), G - 1);
            int gj = (int)(ty * (float)G); gj = min(max(gj, 0), G - 1);
            sgi[sc][n] = (unsigned char)gi;
            sgj[sc][n] = (unsigned char)gj;
            #pragma unroll
            for (int a = 0; a < 3; a++) {
                float rw = gw * c_ranchors[sc][a][0];
                float rh = gh * c_ranchors[sc][a][1];
                if (rw < 4.f && rw > 0.25f && rh < 4.f && rh > 0.25f)
                    bits |= (1u << (sc * 3 + a));
            }
        }
        skeep[n] = (unsigned short)bits;
    }
    __syncthreads();

    // ---------------- Phase A: issue all gather loads ----------------
    const int p = warp * TOTAL_BLOCKS + bx;   // pair id, spread across blocks
    const bool havepair = (p < 3 * NT);
    int pa = 0, pn = 0, pb = 0, pcls = 0;
    unsigned kb = 0;
    float v[3][3];
    if (havepair) {
        pa = p / NT; pn = p - pa * NT;
        pb = sbi[pn]; pcls = scls[pn];
        unsigned bits = skeep[pn];
        #pragma unroll
        for (int sc = 0; sc < 3; sc++) {
            if (bits & (1u << (sc * 3 + pa))) {
                kb |= (1u << sc);
                const float* pred = (sc == 0) ? p0 : ((sc == 1) ? p1 : p2);
                const int G  = c_G[sc];
                const int GG = G * G;
                const int gi = sgi[sc][pn], gj = sgj[sc][pn];
                const float* base = pred + ((long)pb * 255 + (long)pa * 85) * GG
                                         + (long)gj * G + gi;
                v[sc][0] = __ldg(base + (long)lane * GG);
                v[sc][1] = __ldg(base + (long)(lane + 32) * GG);
                v[sc][2] = (lane < 21) ? __ldg(base + (long)(lane + 64) * GG) : 0.0f;
            }
        }
    }

    // ---------------- Phase B: obj softplus sweep (covers gather latency) ----
    {
        float osum[3] = {0.f, 0.f, 0.f};
        #pragma unroll
        for (int k = 0; k < 3; k++) {
            int i = k * OBJ_STRIDE + bx * BLOCK + tid;
            if (i < OBJ_TOTAL4) {
                if (i < 76800)       osum[0] += obj_elem<1600>(p0, i);
                else if (i < 96000)  osum[1] += obj_elem<400>(p1, i - 76800);
                else                 osum[2] += obj_elem<100>(p2, i - 96000);
            }
        }
        #pragma unroll
        for (int s = 0; s < 3; s++) {
            #pragma unroll
            for (int o = 16; o > 0; o >>= 1)
                osum[s] += __shfl_down_sync(0xFFFFFFFF, osum[s], o);
            if (lane == 0 && osum[s] != 0.f) atomicAdd(&sacc[s], (double)osum[s]);
        }
    }

    // ---------------- Phase C: consume gathers ----------------
    if (havepair && kb) {
        #pragma unroll
        for (int sc = 0; sc < 3; sc++) {
            if (!(kb & (1u << sc))) continue;   // warp-uniform

            const int   G  = c_G[sc];
            const float stride = c_stride[sc];
            const int gi = sgi[sc][pn], gj = sgj[sc][pn];

            // lane-parallel dedup: any earlier kept target mapping to same cell?
            bool notfirst = false;
            for (int m2b = 0; m2b < pn; m2b += 32) {
                int m2 = m2b + lane;
                bool m = false;
                if (m2 < pn && (skeep[m2] & (1u << (sc * 3 + pa))) &&
                    sbi[m2] == pb && sgi[sc][m2] == gi && sgj[sc][m2] == gj)
                    m = true;
                if (__any_sync(0xFFFFFFFF, m)) { notfirst = true; break; }
            }

            // cls BCE: per-lane product-of-(1+e^-|x|) + one log
            float v0 = v[sc][0], v1 = v[sc][1], v2 = v[sc][2];
            float mx = 0.f, pr = 1.f, sub = 0.f;
            if (lane >= 5) {
                mx += fmaxf(v0, 0.f);
                pr *= (1.f + __expf(-fabsf(v0)));
                if (lane - 5 == pcls) sub += v0;
            }
            mx += fmaxf(v1, 0.f);
            pr *= (1.f + __expf(-fabsf(v1)));
            if (lane + 27 == pcls) sub += v1;
            if (lane < 21) {
                mx += fmaxf(v2, 0.f);
                pr *= (1.f + __expf(-fabsf(v2)));
                if (lane + 59 == pcls) sub += v2;
            }
            float csum = mx + __logf(pr) - sub;
            #pragma unroll
            for (int o = 16; o > 0; o >>= 1)
                csum += __shfl_down_sync(0xFFFFFFFF, csum, o);

            float obj = __shfl_sync(0xFFFFFFFF, v0, 0);
            float px  = __shfl_sync(0xFFFFFFFF, v0, 1);
            float py  = __shfl_sync(0xFFFFFFFF, v0, 2);
            float pw  = __shfl_sync(0xFFFFFFFF, v0, 3);
            float ph  = __shfl_sync(0xFFFFFFFF, v0, 4);

            if (lane == 0) {
                float cx = scx[pn] * (float)G;
                float cy = scy[pn] * (float)G;
                float pcx = sigmoidf(px) + (float)gi;
                float pcy = sigmoidf(py) + (float)gj;
                float aw = c_anchors[sc][pa][0] / stride;
                float ah = c_anchors[sc][pa][1] / stride;
                float pbw = __expf(fminf(fmaxf(pw, -4.0f), 4.0f)) * aw;
                float pbh = __expf(fminf(fmaxf(ph, -4.0f), 4.0f)) * ah;

                float b1x0 = (pcx - pbw * 0.5f) * stride;
                float b1y0 = (pcy - pbh * 0.5f) * stride;
                float b1x1 = (pcx + pbw * 0.5f) * stride;
                float b1y1 = (pcy + pbh * 0.5f) * stride;

                float tgw = sgw[pn] * (float)G;
                float tgh = sgh[pn] * (float)G;
                float b2x0 = (cx - tgw * 0.5f) * stride;
                float b2y0 = (cy - tgh * 0.5f) * stride;
                float b2x1 = (cx + tgw * 0.5f) * stride;
                float b2y1 = (cy + tgh * 0.5f) * stride;

                const float eps = 1e-7f;
                float w1 = b1x1 - b1x0, h1 = b1y1 - b1y0;
                float w2 = b2x1 - b2x0, h2 = b2y1 - b2y0;
                float ix = fmaxf(fminf(b1x1, b2x1) - fmaxf(b1x0, b2x0), 0.0f);
                float iy = fmaxf(fminf(b1y1, b2y1) - fmaxf(b1y0, b2y0), 0.0f);
                float inter = ix * iy;
                float uni = w1 * h1 + w2 * h2 - inter + eps;
                float iou = inter / uni;
                float cw = fmaxf(b1x1, b2x1) - fminf(b1x0, b2x0);
                float ch = fmaxf(b1y1, b2y1) - fminf(b1y0, b2y0);
                float c2 = cw * cw + ch * ch + eps;
                float dx = b2x0 + b2x1 - b1x0 - b1x1;
                float dy = b2y0 + b2y1 - b1y0 - b1y1;
                float rho2 = (dx * dx + dy * dy) * 0.25f;
                const float k4pi2 = 4.0f / (float)(M_PI * M_PI);
                float da = atanf(w2 / (h2 + eps)) - atanf(w1 / (h1 + eps));
                float vv = k4pi2 * da * da;
                float alpha = vv / (vv - iou + (1.0f + eps));
                float ciou = iou - (rho2 / c2 + vv * alpha);

                atomicAdd(&sacc[12 + sc], 1.0);
                atomicAdd(&sacc[6 + sc],  (double)(1.0f - ciou));
                atomicAdd(&sacc[9 + sc],  (double)csum);
                if (!notfirst) atomicAdd(&sacc[3 + sc], (double)obj);
            }
        }
    }
    __syncthreads();

    // ---------------- Flush block accumulators ----------------
    if (tid < 15 && sacc[tid] != 0.0)
        atomicAdd(&g_acc[tid], sacc[tid]);
    __threadfence();
    __syncthreads();

    // ---------------- Finalize ----------------
    if (tid == 0) {
        unsigned int old = atomicAdd(&g_done, 1);
        if (old == TOTAL_BLOCKS - 1) {
            volatile double* A = g_acc;
            double tot = 0.0;
            #pragma unroll
            for (int s2 = 0; s2 < 3; s2++) {
                double G2 = (double)c_G[s2] * (double)c_G[s2];
                double M  = 48.0 * G2;
                double nk = fmax(A[12 + s2], 1.0);
                double lb = A[6 + s2] / nk;
                double lo = (A[s2] - A[3 + s2]) / M;
                double lc = A[9 + s2] / (nk * (double)NCC);
                tot += 0.05 * lb + 1.0 * lo + 0.5 * lc;
            }
            out[0] = (float)tot;
            #pragma unroll
            for (int i = 0; i < 16; i++) g_acc[i] = 0.0;
            g_done = 0;
            __threadfence();
        }
    }
}

extern "C" void kernel_launch(void* const* d_in, const int* in_sizes, int n_in,
                              void* d_out, int out_size)
{
    const float* p0  = (const float*)d_in[0];
    const float* p1  = (const float*)d_in[1];
    const float* p2  = (const float*)d_in[2];
    const float* tgt = (const float*)d_in[3];
    float* out = (float*)d_out;

    fused_loss_kernel<<<TOTAL_BLOCKS, BLOCK>>>(p0, p1, p2, tgt, out);
}

// round 12
// speedup vs baseline: 4.4543x; 1.2895x over previous
#include <cuda_runtime.h>
#include <math.h>

#define NT   300
#define NCC  80
#define IMGS 640.0f

#define TOTAL_BLOCKS 441           // 3 blocks / SM on 147+ SMs
#define BLOCK 256                  // 8 warps -> 24 warps/SM resident
#define OBJ_TOTAL4 100800          // float4 count across all obj channels

// accumulators: [0..2]=sp  [3..5]=objsub  [6..8]=box  [9..11]=cls  [12..14]=nkeep
__device__ double g_acc[16] = {0};
__device__ unsigned int g_done = 0;

__constant__ float c_anchors[3][3][2] = {
    {{10.f,13.f},{16.f,30.f},{33.f,23.f}},
    {{30.f,61.f},{62.f,45.f},{59.f,119.f}},
    {{116.f,90.f},{156.f,198.f},{373.f,326.f}}
};
__constant__ float c_ranchors[3][3][2] = {
    {{1.f/10.f,1.f/13.f},{1.f/16.f,1.f/30.f},{1.f/33.f,1.f/23.f}},
    {{1.f/30.f,1.f/61.f},{1.f/62.f,1.f/45.f},{1.f/59.f,1.f/119.f}},
    {{1.f/116.f,1.f/90.f},{1.f/156.f,1.f/198.f},{1.f/373.f,1.f/326.f}}
};
__constant__ float c_stride[3] = {8.f, 16.f, 32.f};
__constant__ int   c_G[3]      = {80, 40, 20};

__device__ __forceinline__ float sigmoidf(float x) {
    return 1.0f / (1.0f + __expf(-x));
}
// sum of softplus over a float4, one log for four elements
__device__ __forceinline__ float sp4(const float4 v) {
    float m = fmaxf(v.x, 0.f) + fmaxf(v.y, 0.f) + fmaxf(v.z, 0.f) + fmaxf(v.w, 0.f);
    float pr = (1.f + __expf(-fabsf(v.x))) * (1.f + __expf(-fabsf(v.y)))
             * (1.f + __expf(-fabsf(v.z))) * (1.f + __expf(-fabsf(v.w)));
    return m + __logf(pr);
}

template<int GG4>
__device__ __forceinline__ float obj_elem(const float* __restrict__ pred, int j) {
    int plane = j / GG4;              // compile-time divisor
    int w4 = j - plane * GG4;
    const float4 v = *(const float4*)(pred + (long)plane * (340 * GG4) + 4 * w4);
    return sp4(v);
}

__global__ void __launch_bounds__(BLOCK)
fused_loss_kernel(const float* __restrict__ p0,
                  const float* __restrict__ p1,
                  const float* __restrict__ p2,
                  const float* __restrict__ tgt,
                  float* __restrict__ out)
{
    const int tid  = threadIdx.x;
    const int bx   = blockIdx.x;
    const int warp = tid >> 5, lane = tid & 31;

    __shared__ float  scx[NT], scy[NT], sgw[NT], sgh[NT];   // normalized
    __shared__ short  sbi[NT], scls[NT];
    __shared__ unsigned char sgi[3][NT], sgj[3][NT];
    __shared__ unsigned short skeep[NT];                     // 9 bits: sc*3+a
    __shared__ double sacc[15];

    if (tid < 15) sacc[tid] = 0.0;

    // ---------------- Phase 0: stage targets ----------------
    for (int n = tid; n < NT; n += BLOCK) {
        float bi = tgt[n * 6 + 0];
        float cl = tgt[n * 6 + 1];
        float tx = tgt[n * 6 + 2];
        float ty = tgt[n * 6 + 3];
        float tw = tgt[n * 6 + 4];
        float th = tgt[n * 6 + 5];
        sbi[n] = (short)bi; scls[n] = (short)cl;
        scx[n] = tx; scy[n] = ty; sgw[n] = tw; sgh[n] = th;
        float gw = tw * IMGS, gh = th * IMGS;
        unsigned bits = 0;
        #pragma unroll
        for (int sc = 0; sc < 3; sc++) {
            const int G = c_G[sc];
            int gi = (int)(tx * (float)G); gi = min(max(gi, 0), G - 1);
            int gj = (int)(ty * (float)G); gj = min(max(gj, 0), G - 1);
            sgi[sc][n] = (unsigned char)gi;
            sgj[sc][n] = (unsigned char)gj;
            #pragma unroll
            for (int a = 0; a < 3; a++) {
                float rw = gw * c_ranchors[sc][a][0];
                float rh = gh * c_ranchors[sc][a][1];
                if (rw < 4.f && rw > 0.25f && rh < 4.f && rh > 0.25f)
                    bits |= (1u << (sc * 3 + a));
            }
        }
        skeep[n] = (unsigned short)bits;
    }
    __syncthreads();

    // ---------------- Phase A: one (scale,anchor,target) unit per warp --------
    const int u = warp * TOTAL_BLOCKS + bx;   // unit id, spread across blocks
    int sc = 0, pa = 0, pn = 0, pb = 0, pcls = 0;
    bool kept = false;
    float v0 = 0.f, v1 = 0.f, v2 = 0.f;
    if (u < 2700) {
        sc = u / 900;
        int r = u - sc * 900;
        pa = r / NT; pn = r - pa * NT;
        if (skeep[pn] & (1u << (sc * 3 + pa))) {
            kept = true;
            pb = sbi[pn]; pcls = scls[pn];
            const float* pred = (sc == 0) ? p0 : ((sc == 1) ? p1 : p2);
            const int G  = c_G[sc];
            const int GG = G * G;
            const int gi = sgi[sc][pn], gj = sgj[sc][pn];
            const float* base = pred + ((long)pb * 255 + (long)pa * 85) * GG
                                     + (long)gj * G + gi;
            v0 = __ldg(base + (long)lane * GG);
            v1 = __ldg(base + (long)(lane + 32) * GG);
            v2 = (lane < 21) ? __ldg(base + (long)(lane + 64) * GG) : 0.0f;
        }
    }

    // ---------------- Phase B: obj softplus sweep (one float4/thread) ---------
    {
        float osum[3] = {0.f, 0.f, 0.f};
        int i = bx * BLOCK + tid;             // [0, 112896)
        if (i < OBJ_TOTAL4) {
            if (i < 76800)       osum[0] += obj_elem<1600>(p0, i);
            else if (i < 96000)  osum[1] += obj_elem<400>(p1, i - 76800);
            else                 osum[2] += obj_elem<100>(p2, i - 96000);
        }
        #pragma unroll
        for (int s = 0; s < 3; s++) {
            #pragma unroll
            for (int o = 16; o > 0; o >>= 1)
                osum[s] += __shfl_down_sync(0xFFFFFFFF, osum[s], o);
            if (lane == 0 && osum[s] != 0.f) atomicAdd(&sacc[s], (double)osum[s]);
        }
    }

    // ---------------- Phase C: consume gather ----------------
    if (kept) {
        const int   G  = c_G[sc];
        const float stride = c_stride[sc];
        const int gi = sgi[sc][pn], gj = sgj[sc][pn];

        // lane-parallel dedup: any earlier kept target mapping to same cell?
        bool notfirst = false;
        for (int m2b = 0; m2b < pn; m2b += 32) {
            int m2 = m2b + lane;
            bool m = false;
            if (m2 < pn && (skeep[m2] & (1u << (sc * 3 + pa))) &&
                sbi[m2] == pb && sgi[sc][m2] == gi && sgj[sc][m2] == gj)
                m = true;
            if (__any_sync(0xFFFFFFFF, m)) { notfirst = true; break; }
        }

        // cls BCE: per-lane product-of-(1+e^-|x|) + one log
        float mx = 0.f, pr = 1.f, sub = 0.f;
        if (lane >= 5) {
            mx += fmaxf(v0, 0.f);
            pr *= (1.f + __expf(-fabsf(v0)));
            if (lane - 5 == pcls) sub += v0;
        }
        mx += fmaxf(v1, 0.f);
        pr *= (1.f + __expf(-fabsf(v1)));
        if (lane + 27 == pcls) sub += v1;
        if (lane < 21) {
            mx += fmaxf(v2, 0.f);
            pr *= (1.f + __expf(-fabsf(v2)));
            if (lane + 59 == pcls) sub += v2;
        }
        float csum = mx + __logf(pr) - sub;
        #pragma unroll
        for (int o = 16; o > 0; o >>= 1)
            csum += __shfl_down_sync(0xFFFFFFFF, csum, o);

        float obj = __shfl_sync(0xFFFFFFFF, v0, 0);
        float px  = __shfl_sync(0xFFFFFFFF, v0, 1);
        float py  = __shfl_sync(0xFFFFFFFF, v0, 2);
        float pw  = __shfl_sync(0xFFFFFFFF, v0, 3);
        float ph  = __shfl_sync(0xFFFFFFFF, v0, 4);

        if (lane == 0) {
            float cx = scx[pn] * (float)G;
            float cy = scy[pn] * (float)G;
            float pcx = sigmoidf(px) + (float)gi;
            float pcy = sigmoidf(py) + (float)gj;
            float aw = c_anchors[sc][pa][0] / stride;
            float ah = c_anchors[sc][pa][1] / stride;
            float pbw = __expf(fminf(fmaxf(pw, -4.0f), 4.0f)) * aw;
            float pbh = __expf(fminf(fmaxf(ph, -4.0f), 4.0f)) * ah;

            float b1x0 = (pcx - pbw * 0.5f) * stride;
            float b1y0 = (pcy - pbh * 0.5f) * stride;
            float b1x1 = (pcx + pbw * 0.5f) * stride;
            float b1y1 = (pcy + pbh * 0.5f) * stride;

            float tgw = sgw[pn] * (float)G;
            float tgh = sgh[pn] * (float)G;
            float b2x0 = (cx - tgw * 0.5f) * stride;
            float b2y0 = (cy - tgh * 0.5f) * stride;
            float b2x1 = (cx + tgw * 0.5f) * stride;
            float b2y1 = (cy + tgh * 0.5f) * stride;

            const float eps = 1e-7f;
            float w1 = b1x1 - b1x0, h1 = b1y1 - b1y0;
            float w2 = b2x1 - b2x0, h2 = b2y1 - b2y0;
            float ix = fmaxf(fminf(b1x1, b2x1) - fmaxf(b1x0, b2x0), 0.0f);
            float iy = fmaxf(fminf(b1y1, b2y1) - fmaxf(b1y0, b2y0), 0.0f);
            float inter = ix * iy;
            float uni = w1 * h1 + w2 * h2 - inter + eps;
            float iou = inter / uni;
            float cw = fmaxf(b1x1, b2x1) - fminf(b1x0, b2x0);
            float ch = fmaxf(b1y1, b2y1) - fminf(b1y0, b2y0);
            float c2 = cw * cw + ch * ch + eps;
            float dx = b2x0 + b2x1 - b1x0 - b1x1;
            float dy = b2y0 + b2y1 - b1y0 - b1y1;
            float rho2 = (dx * dx + dy * dy) * 0.25f;
            const float k4pi2 = 4.0f / (float)(M_PI * M_PI);
            float da = atanf(w2 / (h2 + eps)) - atanf(w1 / (h1 + eps));
            float vv = k4pi2 * da * da;
            float alpha = vv / (vv - iou + (1.0f + eps));
            float ciou = iou - (rho2 / c2 + vv * alpha);

            atomicAdd(&sacc[12 + sc], 1.0);
            atomicAdd(&sacc[6 + sc],  (double)(1.0f - ciou));
            atomicAdd(&sacc[9 + sc],  (double)csum);
            if (!notfirst) atomicAdd(&sacc[3 + sc], (double)obj);
        }
    }
    __syncthreads();

    // ---------------- Flush block accumulators ----------------
    if (tid < 15 && sacc[tid] != 0.0)
        atomicAdd(&g_acc[tid], sacc[tid]);
    __threadfence();
    __syncthreads();

    // ---------------- Finalize ----------------
    if (tid == 0) {
        unsigned int old = atomicAdd(&g_done, 1);
        if (old == TOTAL_BLOCKS - 1) {
            volatile double* A = g_acc;
            double tot = 0.0;
            #pragma unroll
            for (int s2 = 0; s2 < 3; s2++) {
                double G2 = (double)c_G[s2] * (double)c_G[s2];
                double M  = 48.0 * G2;
                double nk = fmax(A[12 + s2], 1.0);
                double lb = A[6 + s2] / nk;
                double lo = (A[s2] - A[3 + s2]) / M;
                double lc = A[9 + s2] / (nk * (double)NCC);
                tot += 0.05 * lb + 1.0 * lo + 0.5 * lc;
            }
            out[0] = (float)tot;
            #pragma unroll
            for (int i = 0; i < 16; i++) g_acc[i] = 0.0;
            g_done = 0;
            __threadfence();
        }
    }
}

extern "C" void kernel_launch(void* const* d_in, const int* in_sizes, int n_in,
                              void* d_out, int out_size)
{
    const float* p0  = (const float*)d_in[0];
    const float* p1  = (const float*)d_in[1];
    const float* p2  = (const float*)d_in[2];
    const float* tgt = (const float*)d_in[3];
    float* out = (float*)d_out;

    fused_loss_kernel<<<TOTAL_BLOCKS, BLOCK>>>(p0, p1, p2, tgt, out);
}